// round 15
// baseline (speedup 1.0000x reference)
#include <cuda_runtime.h>
#include <cuda_bf16.h>
#include <math.h>

#define BB 4
#define LL 64
#define DD 64
#define RELN 16
#define NEGV (-1e9f)
#define LOSS_SCALE 4398046511104.0   // 2^42

// ---------------- fast math helpers ------------------------------------------
__device__ __forceinline__ float rcpa(float x) {
    float y; asm("rcp.approx.f32 %0, %1;" : "=f"(y) : "f"(x)); return y;
}
__device__ __forceinline__ float tanh_hw(float x) {
    float y; asm("tanh.approx.f32 %0, %1;" : "=f"(y) : "f"(x)); return y;
}
__device__ __forceinline__ float tanha(float x) { return tanh_hw(x); }
__device__ __forceinline__ float sigm(float x) {
    return fmaf(0.5f, tanh_hw(0.5f * x), 0.5f);
}

// ---------------- packed f32x2 FMA helpers ------------------------------------
__device__ __forceinline__ void fma2(unsigned long long& d,
                                     unsigned long long a, unsigned long long b) {
    asm("fma.rn.f32x2 %0, %1, %2, %0;" : "+l"(d) : "l"(a), "l"(b));
}
__device__ __forceinline__ void unpack2(unsigned long long v, float& x, float& y) {
    asm("mov.b64 {%0,%1}, %2;" : "=f"(x), "=f"(y) : "l"(v));
}
__device__ __forceinline__ float dot64(const ulonglong2* __restrict__ a,
                                       const ulonglong2* __restrict__ b) {
    unsigned long long a0 = 0ULL, a1 = 0ULL, a2 = 0ULL, a3 = 0ULL;
#pragma unroll
    for (int q = 0; q < 16; q += 2) {
        ulonglong2 x = a[q], y = b[q];
        ulonglong2 x2 = a[q + 1], y2 = b[q + 1];
        fma2(a0, x.x, y.x);  fma2(a1, x.y, y.y);
        fma2(a2, x2.x, y2.x); fma2(a3, x2.y, y2.y);
    }
    float s0, s1, s2, s3, s4, s5, s6, s7;
    unpack2(a0, s0, s1); unpack2(a1, s2, s3);
    unpack2(a2, s4, s5); unpack2(a3, s6, s7);
    return ((s0 + s1) + (s2 + s3)) + ((s4 + s5) + (s6 + s7));
}
// 16-float quarter dot via packed FMAs (a, b 16B-aligned)
__device__ __forceinline__ float dot16(const ulonglong2* __restrict__ a,
                                       const ulonglong2* __restrict__ b) {
    unsigned long long a0 = 0ULL, a1 = 0ULL;
#pragma unroll
    for (int qq = 0; qq < 4; qq++) {
        ulonglong2 x = a[qq], y = b[qq];
        fma2(a0, x.x, y.x); fma2(a1, x.y, y.y);
    }
    float s0, s1, s2, s3;
    unpack2(a0, s0, s1); unpack2(a1, s2, s3);
    return (s0 + s1) + (s2 + s3);
}

// ---------------- scratch ------------------------------------------------------
__device__ __align__(16) float g_o[BB * LL * DD];
__device__ __align__(16) float g_v[BB * RELN * LL * DD];
__device__ __align__(16) float g_gx[BB * LL * 3 * DD];
__device__ unsigned long long g_lossint;
__device__ unsigned int g_loss;

// ---------------- KA: relation matvec, quarter-split rows (R12-proven) --------
__global__ void __launch_bounds__(256)
ka_embed_relmat(const int* __restrict__ x,
                const float* __restrict__ emb,
                const float* __restrict__ rel) {
    int blk = blockIdx.x;
    int b = blk >> 6;
    int k = (blk >> 2) & 15;
    int q4 = blk & 3;
    int tid = threadIdx.x;
    int jslab = q4 * 16;

    if (k == 0) {
        for (int idx = tid; idx < 16 * DD; idx += 256) {
            int row = jslab + (idx >> 6);
            int d   = idx & 63;
            g_o[b * LL * DD + row * DD + d] = emb[x[b * LL + row] * DD + d];
        }
        return;
    }

    __shared__ __align__(16) float so[16 * DD];
    for (int idx = tid; idx < 16 * DD; idx += 256) {
        int row = jslab + (idx >> 6);
        so[idx] = emb[x[b * LL + row] * DD + (idx & 63)];
    }
    __syncthreads();

    int d  = tid >> 2;
    int qt = tid & 3;
    ulonglong2 m[4];
    const ulonglong2* mrow =
        reinterpret_cast<const ulonglong2*>(rel + (k * DD + d) * DD + qt * 16);
#pragma unroll
    for (int qq = 0; qq < 4; qq++) m[qq] = mrow[qq];

    float* vbase = g_v + (((b * RELN + k) * LL + jslab) * DD) + d;
#pragma unroll
    for (int jj = 0; jj < 16; jj++) {
        float sum = dot16(m, reinterpret_cast<const ulonglong2*>(so + jj * DD + qt * 16));
        sum += __shfl_xor_sync(0xFFFFFFFFu, sum, 1);
        sum += __shfl_xor_sync(0xFFFFFFFFu, sum, 2);
        if (qt == 0) vbase[jj * DD] = sum;
    }
}

// ---------------- KB: attention column, quarter-split projections -------------
__global__ void __launch_bounds__(64)
kb_attn(const int* __restrict__ r,
        const float* __restrict__ attW,
        const float* __restrict__ attb,
        const float* __restrict__ gWih,
        const float* __restrict__ gbih) {
    int b = blockIdx.x >> 6;
    int i = blockIdx.x & 63;
    int tid = threadIdx.x;   // 64

    __shared__ float sob[LL][DD + 1];
    __shared__ __align__(16) float soi[DD];
    __shared__ float sp[LL];
    __shared__ __align__(16) float sctx[DD];
    __shared__ __align__(16) float so2[DD];
    __shared__ float wmax[2], wsum[2];

    // vectorized staged load: 16 rounds of LDG.128
    const float4* ob4 = reinterpret_cast<const float4*>(g_o + b * LL * DD);
    for (int idx = tid; idx < LL * DD / 4; idx += 64) {
        float4 vv = ob4[idx];
        int row = idx >> 4;
        int c4  = (idx & 15) * 4;
        sob[row][c4]     = vv.x;
        sob[row][c4 + 1] = vv.y;
        sob[row][c4 + 2] = vv.z;
        sob[row][c4 + 3] = vv.w;
    }
    __syncthreads();
    soi[tid] = sob[i][tid];
    __syncthreads();

    int j = tid;
    int rj = r[(b * LL + i) * LL + j];
    float s;
    if (rj > 0) {
        s = dot64(reinterpret_cast<const ulonglong2*>(
                      g_v + (((b * RELN + rj) * LL + j) * DD)),
                  reinterpret_cast<const ulonglong2*>(soi));
    } else {
        s = NEGV;
    }

    float mx = s;
#pragma unroll
    for (int off = 16; off; off >>= 1) mx = fmaxf(mx, __shfl_xor_sync(0xFFFFFFFFu, mx, off));
    if ((tid & 31) == 0) wmax[tid >> 5] = mx;
    __syncthreads();
    mx = fmaxf(wmax[0], wmax[1]);
    float e = __expf(s - mx);
    float ss = e;
#pragma unroll
    for (int off = 16; off; off >>= 1) ss += __shfl_xor_sync(0xFFFFFFFFu, ss, off);
    if ((tid & 31) == 0) wsum[tid >> 5] = ss;
    __syncthreads();
    float inv = rcpa(wsum[0] + wsum[1]);
    sp[tid] = e * inv;
    __syncthreads();

    {
        float acc = 0.f;
        for (int jj = 0; jj < LL; jj++) acc += sp[jj] * sob[jj][tid];
        sctx[tid] = acc;
    }
    __syncthreads();

    // attW projection: quarter-split, 4 passes
    int dq = tid >> 2;       // 0..15
    int qt = tid & 3;
    const ulonglong2* cq = reinterpret_cast<const ulonglong2*>(sctx + qt * 16);
#pragma unroll
    for (int p = 0; p < 4; p++) {
        int d = p * 16 + dq;
        float sum = dot16(reinterpret_cast<const ulonglong2*>(attW + d * DD + qt * 16), cq);
        sum += __shfl_xor_sync(0xFFFFFFFFu, sum, 1);
        sum += __shfl_xor_sync(0xFFFFFFFFu, sum, 2);
        if (qt == 0) so2[d] = attb[d] + sum;
    }
    __syncthreads();

    // gWih projection: quarter-split, 12 passes
    const ulonglong2* oq = reinterpret_cast<const ulonglong2*>(so2 + qt * 16);
    float* gxout = g_gx + (b * LL + i) * (3 * DD);
#pragma unroll
    for (int p = 0; p < 12; p++) {
        int g = p * 16 + dq;
        float sum = dot16(reinterpret_cast<const ulonglong2*>(gWih + g * DD + qt * 16), oq);
        sum += __shfl_xor_sync(0xFFFFFFFFu, sum, 1);
        sum += __shfl_xor_sync(0xFFFFFFFFu, sum, 2);
        if (qt == 0) gxout[g] = gbih[g] + sum;
    }
}

// ---------------- KC: single-barrier GRU + tail + loss ------------------------
__global__ void __launch_bounds__(64)
kc_fused(const float* __restrict__ Whh, const float* __restrict__ bhh,
         const int* __restrict__ lv, const int* __restrict__ yv,
         const float* __restrict__ oWih, const float* __restrict__ oWhh,
         const float* __restrict__ obih, const float* __restrict__ obhh,
         const float* __restrict__ W1, const float* __restrict__ b1,
         const float* __restrict__ W2, const float* __restrict__ b2,
         float* __restrict__ out, int out_size) {
    int b = blockIdx.x;
    int k = threadIdx.x;   // 0..63

    __shared__ __align__(16) float shseq[LL][DD];
    __shared__ float sga[LL][3];
    __shared__ float sa[LL];
    __shared__ float sw[LL];
    __shared__ __align__(16) float sc[DD];
    __shared__ __align__(16) float sh1[DD / 2];
    __shared__ float slog[2];
    __shared__ float wred[4];
    __shared__ int smaxl;

    ulonglong2 wR[16], wZ[16], wN[16];
    {
        const ulonglong2* p0 = reinterpret_cast<const ulonglong2*>(Whh + k * DD);
        const ulonglong2* p1 = reinterpret_cast<const ulonglong2*>(Whh + (DD + k) * DD);
        const ulonglong2* p2 = reinterpret_cast<const ulonglong2*>(Whh + (2 * DD + k) * DD);
#pragma unroll
        for (int q = 0; q < 16; q++) { wR[q] = p0[q]; wZ[q] = p1[q]; wN[q] = p2[q]; }
    }
    float bR = bhh[k], bZ = bhh[DD + k], bN = bhh[2 * DD + k];

    if (k == 0) {
        int m = lv[0];
#pragma unroll
        for (int i = 1; i < BB; i++) m = max(m, lv[i]);
        smaxl = m + 1;
    }

    const float* gxb = g_gx + b * LL * (3 * DD);
    float xr = gxb[k], xz = gxb[DD + k], xn = gxb[2 * DD + k];
    float hown = 0.f;

    // step 0: h = 0 -> gh = bhh
    {
        float rg = sigm(xr + bR);
        float zg = sigm(xz + bZ);
        float ng = tanha(xn + rg * bN);
        hown = (1.f - zg) * ng;
        shseq[0][k] = hown;
        const float* nx = gxb + 3 * DD;
        xr = nx[k]; xz = nx[DD + k]; xn = nx[2 * DD + k];
    }
    __syncthreads();

    // steps 1..63: ONE barrier per step, h read from shseq[l-1]
    for (int l = 1; l < LL; l++) {
        const ulonglong2* h2 = reinterpret_cast<const ulonglong2*>(shseq[l - 1]);
        unsigned long long aR0 = 0ULL, aR1 = 0ULL, aZ0 = 0ULL, aZ1 = 0ULL,
                           aN0 = 0ULL, aN1 = 0ULL;
#pragma unroll
        for (int q = 0; q < 16; q++) {
            ulonglong2 hq = h2[q];
            fma2(aR0, wR[q].x, hq.x); fma2(aR1, wR[q].y, hq.y);
            fma2(aZ0, wZ[q].x, hq.x); fma2(aZ1, wZ[q].y, hq.y);
            fma2(aN0, wN[q].x, hq.x); fma2(aN1, wN[q].y, hq.y);
        }
        float r0, r1, r2, r3, z0, z1, z2, z3, n0, n1, n2, n3;
        unpack2(aR0, r0, r1); unpack2(aR1, r2, r3);
        unpack2(aZ0, z0, z1); unpack2(aZ1, z2, z3);
        unpack2(aN0, n0, n1); unpack2(aN1, n2, n3);
        float hr = bR + (r0 + r1) + (r2 + r3);
        float hz = bZ + (z0 + z1) + (z2 + z3);
        float hn = bN + (n0 + n1) + (n2 + n3);
        float rg = sigm(xr + hr);
        float zg = sigm(xz + hz);
        float ng = tanha(xn + rg * hn);
        hown = (1.f - zg) * ng + zg * hown;
        shseq[l][k] = hown;
        if (l + 1 < LL) {
            const float* nx = gxb + (l + 1) * 3 * DD;
            xr = nx[k]; xz = nx[DD + k]; xn = nx[2 * DD + k];
        }
        __syncthreads();
    }

#pragma unroll
    for (int g = 0; g < 3; g++) {
        sga[k][g] = obih[g] +
            dot64(reinterpret_cast<const ulonglong2*>(shseq[k]),
                  reinterpret_cast<const ulonglong2*>(oWih + g * DD));
    }
    __syncthreads();

    if (k == 0) {
        float h = 0.f;
        float w0 = oWhh[0], w1 = oWhh[1], wn = oWhh[2];
        float c0 = obhh[0], c1 = obhh[1], cn = obhh[2];
        for (int l = 0; l < LL; l++) {
            float rg = sigm(sga[l][0] + h * w0 + c0);
            float zg = sigm(sga[l][1] + h * w1 + c1);
            float ng = tanha(sga[l][2] + rg * (h * wn + cn));
            h = (1.f - zg) * ng + zg * h;
            sa[l] = h;
        }
    }
    __syncthreads();

    {
        float v = (k < smaxl) ? sa[k] : NEGV;
        float mx = v;
#pragma unroll
        for (int off = 16; off; off >>= 1)
            mx = fmaxf(mx, __shfl_xor_sync(0xFFFFFFFFu, mx, off));
        if ((k & 31) == 0) wred[k >> 5] = mx;
        sa[k] = v;
    }
    __syncthreads();
    {
        float mx = fmaxf(wred[0], wred[1]);
        float e = __expf(sa[k] - mx);
        float ss = e;
#pragma unroll
        for (int off = 16; off; off >>= 1) ss += __shfl_xor_sync(0xFFFFFFFFu, ss, off);
        if ((k & 31) == 0) wred[2 + (k >> 5)] = ss;
        sw[k] = e;
    }
    __syncthreads();
    {
        float inv = rcpa(wred[2] + wred[3]);
        float acc = 0.f;
#pragma unroll 8
        for (int l = 0; l < LL; l++) acc += sw[l] * shseq[l][k];
        sc[k] = acc * inv;
    }
    __syncthreads();
    if (k < 32) {
        float acc = b1[k] +
            dot64(reinterpret_cast<const ulonglong2*>(W1 + k * DD),
                  reinterpret_cast<const ulonglong2*>(sc));
        sh1[k] = fmaxf(acc, 0.f);
    }
    __syncthreads();
    if (k < 2) {
        const float* wr2 = W2 + k * 32;
        float acc = b2[k];
#pragma unroll
        for (int m = 0; m < 32; m++) acc += sh1[m] * wr2[m];
        slog[k] = acc;
    }
    __syncthreads();

    if (k == 0) {
        float a0 = slog[0], a1 = slog[1];
        float mx = fmaxf(a0, a1);
        float e0 = __expf(a0 - mx), e1 = __expf(a1 - mx);
        float z = e0 + e1;
        float invz = rcpa(z);
        if (2 * b < out_size)     out[2 * b]     = e0 * invz;
        if (2 * b + 1 < out_size) out[2 * b + 1] = e1 * invz;
        float chosen = (yv[b] == 0) ? a0 : a1;
        float t = -(chosen - mx - __logf(z));
        atomicAdd(&g_lossint, (unsigned long long)((double)t * LOSS_SCALE));
        __threadfence();
        unsigned int c = atomicAdd(&g_loss, 1u);
        if (c == 3u) {
            unsigned long long s = atomicAdd(&g_lossint, 0ULL);
            if (out_size > 8)
                out[8] = (float)((double)s * (1.0 / (4.0 * LOSS_SCALE)));
            for (int i = 9; i < out_size; i++) out[i] = 0.f;
            g_loss = 0u; g_lossint = 0ULL;
            __threadfence();
        }
    }
}

// ---------------- launch ------------------------------------------------------
extern "C" void kernel_launch(void* const* d_in, const int* in_sizes, int n_in,
                              void* d_out, int out_size) {
    const int*   x    = (const int*)  d_in[0];
    const int*   y    = (const int*)  d_in[1];
    const int*   r    = (const int*)  d_in[2];
    const int*   l    = (const int*)  d_in[3];
    const float* emb  = (const float*)d_in[4];
    const float* rel  = (const float*)d_in[5];
    const float* attW = (const float*)d_in[6];
    const float* attb = (const float*)d_in[7];
    const float* gWih = (const float*)d_in[8];
    const float* gWhh = (const float*)d_in[9];
    const float* gbih = (const float*)d_in[10];
    const float* gbhh = (const float*)d_in[11];
    const float* oWih = (const float*)d_in[12];
    const float* oWhh = (const float*)d_in[13];
    const float* obih = (const float*)d_in[14];
    const float* obhh = (const float*)d_in[15];
    const float* W1   = (const float*)d_in[16];
    const float* b1   = (const float*)d_in[17];
    const float* W2   = (const float*)d_in[18];
    const float* b2   = (const float*)d_in[19];

    ka_embed_relmat<<<BB * RELN * 4, 256>>>(x, emb, rel);
    kb_attn<<<BB * LL, 64>>>(r, attW, attb, gWih, gbih);
    kc_fused<<<BB, 64>>>(gWhh, gbhh, l, y, oWih, oWhh, obih, obhh,
                         W1, b1, W2, b2, (float*)d_out, out_size);
}

// round 16
// speedup vs baseline: 1.1647x; 1.1647x over previous
#include <cuda_runtime.h>
#include <cuda_bf16.h>
#include <math.h>

#define BB 4
#define LL 64
#define DD 64
#define RELN 16
#define NEGV (-1e9f)
#define LOSS_SCALE 4398046511104.0   // 2^42

// ---------------- fast math helpers ------------------------------------------
__device__ __forceinline__ float rcpa(float x) {
    float y; asm("rcp.approx.f32 %0, %1;" : "=f"(y) : "f"(x)); return y;
}
__device__ __forceinline__ float tanh_hw(float x) {
    float y; asm("tanh.approx.f32 %0, %1;" : "=f"(y) : "f"(x)); return y;
}
__device__ __forceinline__ float tanha(float x) { return tanh_hw(x); }
__device__ __forceinline__ float sigm(float x) {
    return fmaf(0.5f, tanh_hw(0.5f * x), 0.5f);
}

// ---------------- packed f32x2 FMA helpers ------------------------------------
__device__ __forceinline__ void fma2(unsigned long long& d,
                                     unsigned long long a, unsigned long long b) {
    asm("fma.rn.f32x2 %0, %1, %2, %0;" : "+l"(d) : "l"(a), "l"(b));
}
__device__ __forceinline__ void unpack2(unsigned long long v, float& x, float& y) {
    asm("mov.b64 {%0,%1}, %2;" : "=f"(x), "=f"(y) : "l"(v));
}
__device__ __forceinline__ float dot64(const ulonglong2* __restrict__ a,
                                       const ulonglong2* __restrict__ b) {
    unsigned long long a0 = 0ULL, a1 = 0ULL, a2 = 0ULL, a3 = 0ULL;
#pragma unroll
    for (int q = 0; q < 16; q += 2) {
        ulonglong2 x = a[q], y = b[q];
        ulonglong2 x2 = a[q + 1], y2 = b[q + 1];
        fma2(a0, x.x, y.x);  fma2(a1, x.y, y.y);
        fma2(a2, x2.x, y2.x); fma2(a3, x2.y, y2.y);
    }
    float s0, s1, s2, s3, s4, s5, s6, s7;
    unpack2(a0, s0, s1); unpack2(a1, s2, s3);
    unpack2(a2, s4, s5); unpack2(a3, s6, s7);
    return ((s0 + s1) + (s2 + s3)) + ((s4 + s5) + (s6 + s7));
}
__device__ __forceinline__ float dot16(const ulonglong2* __restrict__ a,
                                       const ulonglong2* __restrict__ b) {
    unsigned long long a0 = 0ULL, a1 = 0ULL;
#pragma unroll
    for (int qq = 0; qq < 4; qq++) {
        ulonglong2 x = a[qq], y = b[qq];
        fma2(a0, x.x, y.x); fma2(a1, x.y, y.y);
    }
    float s0, s1, s2, s3;
    unpack2(a0, s0, s1); unpack2(a1, s2, s3);
    return (s0 + s1) + (s2 + s3);
}

// ---------------- scratch ------------------------------------------------------
__device__ __align__(16) float g_o[BB * LL * DD];
__device__ __align__(16) float g_v[BB * RELN * LL * DD];
__device__ __align__(16) float g_gx[BB * LL * 3 * DD];
__device__ unsigned long long g_lossint;
__device__ unsigned int g_loss;
__device__ unsigned int g_kbcnt[BB];   // per-batch attention completion; finisher resets

// ---------------- KA: relation matvec, quarter-split rows (R12-proven) --------
__global__ void __launch_bounds__(256)
ka_embed_relmat(const int* __restrict__ x,
                const float* __restrict__ emb,
                const float* __restrict__ rel) {
    int blk = blockIdx.x;
    int b = blk >> 6;
    int k = (blk >> 2) & 15;
    int q4 = blk & 3;
    int tid = threadIdx.x;
    int jslab = q4 * 16;

    if (k == 0) {
        for (int idx = tid; idx < 16 * DD; idx += 256) {
            int row = jslab + (idx >> 6);
            int d   = idx & 63;
            g_o[b * LL * DD + row * DD + d] = emb[x[b * LL + row] * DD + d];
        }
        return;
    }

    __shared__ __align__(16) float so[16 * DD];
    for (int idx = tid; idx < 16 * DD; idx += 256) {
        int row = jslab + (idx >> 6);
        so[idx] = emb[x[b * LL + row] * DD + (idx & 63)];
    }
    __syncthreads();

    int d  = tid >> 2;
    int qt = tid & 3;
    ulonglong2 m[4];
    const ulonglong2* mrow =
        reinterpret_cast<const ulonglong2*>(rel + (k * DD + d) * DD + qt * 16);
#pragma unroll
    for (int qq = 0; qq < 4; qq++) m[qq] = mrow[qq];

    float* vbase = g_v + (((b * RELN + k) * LL + jslab) * DD) + d;
#pragma unroll
    for (int jj = 0; jj < 16; jj++) {
        float sum = dot16(m, reinterpret_cast<const ulonglong2*>(so + jj * DD + qt * 16));
        sum += __shfl_xor_sync(0xFFFFFFFFu, sum, 1);
        sum += __shfl_xor_sync(0xFFFFFFFFu, sum, 2);
        if (qt == 0) vbase[jj * DD] = sum;
    }
}

// ---------------- K2: attention blocks + per-batch GRU runner blocks ----------
// grid 260, 64 threads. blk<256: R13 kb verbatim (b=blk>>6, i=blk&63), then
// bump g_kbcnt[b]. blk>=256: GRU runner for batch b=blk-256 — preload Whh
// (overlapped with attention), spin to 64, then R13 kc verbatim.
__global__ void __launch_bounds__(64)
k2_attn_gru(const int* __restrict__ r,
            const float* __restrict__ attW, const float* __restrict__ attb,
            const float* __restrict__ gWih, const float* __restrict__ gbih,
            const float* __restrict__ Whh,  const float* __restrict__ bhh,
            const int* __restrict__ lv, const int* __restrict__ yv,
            const float* __restrict__ oWih, const float* __restrict__ oWhh,
            const float* __restrict__ obih, const float* __restrict__ obhh,
            const float* __restrict__ W1, const float* __restrict__ b1,
            const float* __restrict__ W2, const float* __restrict__ b2,
            float* __restrict__ out, int out_size) {
    int blk = blockIdx.x;
    int tid = threadIdx.x;   // 64

    if (blk < BB * LL) {
        // ===================== attention block (R13 kb) ======================
        int b = blk >> 6;
        int i = blk & 63;

        __shared__ float sob[LL][DD + 1];
        __shared__ __align__(16) float soi[DD];
        __shared__ float sp[LL];
        __shared__ __align__(16) float sctx[DD];
        __shared__ __align__(16) float so2[DD];
        __shared__ float wmax[2], wsum[2];

        const float* ob = g_o + b * LL * DD;
        for (int jj = 0; jj < LL; jj++) sob[jj][tid] = ob[jj * DD + tid];
        __syncthreads();
        soi[tid] = sob[i][tid];
        __syncthreads();

        int j = tid;
        int rj = r[(b * LL + i) * LL + j];
        float s;
        if (rj > 0) {
            s = dot64(reinterpret_cast<const ulonglong2*>(
                          g_v + (((b * RELN + rj) * LL + j) * DD)),
                      reinterpret_cast<const ulonglong2*>(soi));
        } else {
            s = NEGV;
        }

        float mx = s;
#pragma unroll
        for (int off = 16; off; off >>= 1)
            mx = fmaxf(mx, __shfl_xor_sync(0xFFFFFFFFu, mx, off));
        if ((tid & 31) == 0) wmax[tid >> 5] = mx;
        __syncthreads();
        mx = fmaxf(wmax[0], wmax[1]);
        float e = __expf(s - mx);
        float ss = e;
#pragma unroll
        for (int off = 16; off; off >>= 1) ss += __shfl_xor_sync(0xFFFFFFFFu, ss, off);
        if ((tid & 31) == 0) wsum[tid >> 5] = ss;
        __syncthreads();
        float inv = rcpa(wsum[0] + wsum[1]);
        sp[tid] = e * inv;
        __syncthreads();

        {
            float acc = 0.f;
            for (int jj = 0; jj < LL; jj++) acc += sp[jj] * sob[jj][tid];
            sctx[tid] = acc;
        }
        __syncthreads();

        so2[tid] = attb[tid] +
                   dot64(reinterpret_cast<const ulonglong2*>(attW + tid * DD),
                         reinterpret_cast<const ulonglong2*>(sctx));
        __syncthreads();

        float* gxout = g_gx + (b * LL + i) * (3 * DD);
#pragma unroll
        for (int gset = 0; gset < 3; gset++) {
            int g = gset * DD + tid;
            gxout[g] = gbih[g] +
                       dot64(reinterpret_cast<const ulonglong2*>(gWih + g * DD),
                             reinterpret_cast<const ulonglong2*>(so2));
        }
        __syncthreads();
        if (tid == 0) { __threadfence(); atomicAdd(&g_kbcnt[b], 1u); }
        return;
    }

    // ======================= GRU runner block (R13 kc) =======================
    int b = blk - BB * LL;
    int k = tid;

    __shared__ __align__(16) float sh[DD];
    __shared__ __align__(16) float shseq[LL][DD];
    __shared__ float sga[LL][3];
    __shared__ float sa[LL];
    __shared__ float sw[LL];
    __shared__ __align__(16) float sc[DD];
    __shared__ __align__(16) float sh1[DD / 2];
    __shared__ float slog[2];
    __shared__ float wred[4];
    __shared__ int smaxl;

    // preload weights while attention blocks run (free overlap)
    ulonglong2 wR[16], wZ[16], wN[16];
    {
        const ulonglong2* p0 = reinterpret_cast<const ulonglong2*>(Whh + k * DD);
        const ulonglong2* p1 = reinterpret_cast<const ulonglong2*>(Whh + (DD + k) * DD);
        const ulonglong2* p2 = reinterpret_cast<const ulonglong2*>(Whh + (2 * DD + k) * DD);
#pragma unroll
        for (int q = 0; q < 16; q++) { wR[q] = p0[q]; wZ[q] = p1[q]; wN[q] = p2[q]; }
    }
    float bR = bhh[k], bZ = bhh[DD + k], bN = bhh[2 * DD + k];

    if (k == 0) {
        int m = lv[0];
#pragma unroll
        for (int i = 1; i < BB; i++) m = max(m, lv[i]);
        smaxl = m + 1;
    }

    // spin for this batch's 64 attention blocks
    if (k == 0) {
        while (*(volatile unsigned int*)&g_kbcnt[b] < 64u) __nanosleep(64);
    }
    __syncthreads();
    __threadfence();

    const float* gxb = g_gx + b * LL * (3 * DD);
    float xr = gxb[k], xz = gxb[DD + k], xn = gxb[2 * DD + k];
    float hown = 0.f;

    {
        float rg = sigm(xr + bR);
        float zg = sigm(xz + bZ);
        float ng = tanha(xn + rg * bN);
        hown = (1.f - zg) * ng;
        sh[k] = hown;
        shseq[0][k] = hown;
        const float* nx = gxb + 3 * DD;
        xr = nx[k]; xz = nx[DD + k]; xn = nx[2 * DD + k];
    }
    __syncthreads();

    for (int l = 1; l < LL; l++) {
        const ulonglong2* h2 = reinterpret_cast<const ulonglong2*>(sh);
        unsigned long long aR0 = 0ULL, aR1 = 0ULL, aZ0 = 0ULL, aZ1 = 0ULL,
                           aN0 = 0ULL, aN1 = 0ULL;
#pragma unroll
        for (int q = 0; q < 16; q++) {
            ulonglong2 hq = h2[q];
            fma2(aR0, wR[q].x, hq.x); fma2(aR1, wR[q].y, hq.y);
            fma2(aZ0, wZ[q].x, hq.x); fma2(aZ1, wZ[q].y, hq.y);
            fma2(aN0, wN[q].x, hq.x); fma2(aN1, wN[q].y, hq.y);
        }
        float r0, r1, r2, r3, z0, z1, z2, z3, n0, n1, n2, n3;
        unpack2(aR0, r0, r1); unpack2(aR1, r2, r3);
        unpack2(aZ0, z0, z1); unpack2(aZ1, z2, z3);
        unpack2(aN0, n0, n1); unpack2(aN1, n2, n3);
        float hr = bR + (r0 + r1) + (r2 + r3);
        float hz = bZ + (z0 + z1) + (z2 + z3);
        float hn = bN + (n0 + n1) + (n2 + n3);
        float rg = sigm(xr + hr);
        float zg = sigm(xz + hz);
        float ng = tanha(xn + rg * hn);
        hown = (1.f - zg) * ng + zg * hown;
        __syncthreads();
        sh[k] = hown;
        shseq[l][k] = hown;
        if (l + 1 < LL) {
            const float* nx = gxb + (l + 1) * 3 * DD;
            xr = nx[k]; xz = nx[DD + k]; xn = nx[2 * DD + k];
        }
        __syncthreads();
    }

#pragma unroll
    for (int g = 0; g < 3; g++) {
        sga[k][g] = obih[g] +
            dot64(reinterpret_cast<const ulonglong2*>(shseq[k]),
                  reinterpret_cast<const ulonglong2*>(oWih + g * DD));
    }
    __syncthreads();

    if (k == 0) {
        float h = 0.f;
        float w0 = oWhh[0], w1 = oWhh[1], wn = oWhh[2];
        float c0 = obhh[0], c1 = obhh[1], cn = obhh[2];
        for (int l = 0; l < LL; l++) {
            float rg = sigm(sga[l][0] + h * w0 + c0);
            float zg = sigm(sga[l][1] + h * w1 + c1);
            float ng = tanha(sga[l][2] + rg * (h * wn + cn));
            h = (1.f - zg) * ng + zg * h;
            sa[l] = h;
        }
    }
    __syncthreads();

    {
        float v = (k < smaxl) ? sa[k] : NEGV;
        float mx = v;
#pragma unroll
        for (int off = 16; off; off >>= 1)
            mx = fmaxf(mx, __shfl_xor_sync(0xFFFFFFFFu, mx, off));
        if ((k & 31) == 0) wred[k >> 5] = mx;
        sa[k] = v;
    }
    __syncthreads();
    {
        float mx = fmaxf(wred[0], wred[1]);
        float e = __expf(sa[k] - mx);
        float ss = e;
#pragma unroll
        for (int off = 16; off; off >>= 1) ss += __shfl_xor_sync(0xFFFFFFFFu, ss, off);
        if ((k & 31) == 0) wred[2 + (k >> 5)] = ss;
        sw[k] = e;
    }
    __syncthreads();
    {
        float inv = rcpa(wred[2] + wred[3]);
        float acc = 0.f;
#pragma unroll 8
        for (int l = 0; l < LL; l++) acc += sw[l] * shseq[l][k];
        sc[k] = acc * inv;
    }
    __syncthreads();
    if (k < 32) {
        float acc = b1[k] +
            dot64(reinterpret_cast<const ulonglong2*>(W1 + k * DD),
                  reinterpret_cast<const ulonglong2*>(sc));
        sh1[k] = fmaxf(acc, 0.f);
    }
    __syncthreads();
    if (k < 2) {
        const float* wr2 = W2 + k * 32;
        float acc = b2[k];
#pragma unroll
        for (int m = 0; m < 32; m++) acc += sh1[m] * wr2[m];
        slog[k] = acc;
    }
    __syncthreads();

    if (k == 0) {
        float a0 = slog[0], a1 = slog[1];
        float mx = fmaxf(a0, a1);
        float e0 = __expf(a0 - mx), e1 = __expf(a1 - mx);
        float z = e0 + e1;
        float invz = rcpa(z);
        if (2 * b < out_size)     out[2 * b]     = e0 * invz;
        if (2 * b + 1 < out_size) out[2 * b + 1] = e1 * invz;
        float chosen = (yv[b] == 0) ? a0 : a1;
        float t = -(chosen - mx - __logf(z));
        atomicAdd(&g_lossint, (unsigned long long)((double)t * LOSS_SCALE));
        __threadfence();
        unsigned int c = atomicAdd(&g_loss, 1u);
        if (c == 3u) {
            unsigned long long s = atomicAdd(&g_lossint, 0ULL);
            if (out_size > 8)
                out[8] = (float)((double)s * (1.0 / (4.0 * LOSS_SCALE)));
            for (int ii = 9; ii < out_size; ii++) out[ii] = 0.f;
            g_loss = 0u; g_lossint = 0ULL;
#pragma unroll
            for (int ii = 0; ii < BB; ii++) g_kbcnt[ii] = 0u;
            __threadfence();
        }
    }
}

// ---------------- launch ------------------------------------------------------
extern "C" void kernel_launch(void* const* d_in, const int* in_sizes, int n_in,
                              void* d_out, int out_size) {
    const int*   x    = (const int*)  d_in[0];
    const int*   y    = (const int*)  d_in[1];
    const int*   r    = (const int*)  d_in[2];
    const int*   l    = (const int*)  d_in[3];
    const float* emb  = (const float*)d_in[4];
    const float* rel  = (const float*)d_in[5];
    const float* attW = (const float*)d_in[6];
    const float* attb = (const float*)d_in[7];
    const float* gWih = (const float*)d_in[8];
    const float* gWhh = (const float*)d_in[9];
    const float* gbih = (const float*)d_in[10];
    const float* gbhh = (const float*)d_in[11];
    const float* oWih = (const float*)d_in[12];
    const float* oWhh = (const float*)d_in[13];
    const float* obih = (const float*)d_in[14];
    const float* obhh = (const float*)d_in[15];
    const float* W1   = (const float*)d_in[16];
    const float* b1   = (const float*)d_in[17];
    const float* W2   = (const float*)d_in[18];
    const float* b2   = (const float*)d_in[19];

    ka_embed_relmat<<<BB * RELN * 4, 256>>>(x, emb, rel);
    k2_attn_gru<<<BB * LL + BB, 64>>>(r, attW, attb, gWih, gbih,
                                      gWhh, gbhh, l, y, oWih, oWhh, obih, obhh,
                                      W1, b1, W2, b2, (float*)d_out, out_size);
}